// round 5
// baseline (speedup 1.0000x reference)
#include <cuda_runtime.h>
#include <cuda_bf16.h>
#include <cstdint>

#define BB 64
#define TT 512
#define HH 300
#define VV 50257

// Scan tiling: thread t in [0,320) ; pair p = t>>1 handles rows {2p, 2p+1},
// half q = t&1 handles k-range [152q, 152q+152) (zero-padded past 300).
// Per half: first 80 k-cols of W in registers, remaining 72 in shared memory.
#define KREG 80            // k-cols per row held in registers (20 float4)
#define KSM  72            // k-cols per row held in smem      (18 float4)
#define NJR  (KREG/4)      // 20
#define NJS  (KSM/4)       // 18
// Warp-interleaved smem W: [warp][j][row_sel][lane] float4
#define WL_F4   (10 * NJS * 2 * 32)            // 11520 float4
#define SCAN_SMEM_BYTES (WL_F4 * 16 + 2 * 304 * 4)

// Scratch (allocation-free: __device__ globals)
__device__ float g_ux[BB * TT * HH];   // [B*T, H] input projections
__device__ float g_h[BB * HH];         // final hidden state

// =====================================================================
// Kernel 1: ux[m, g] = sum_h emb[tokens[m]][h] * U[g][h]
// Tiled SGEMM with gather. CTA tile: 128 m x 128 g, Tk = 8.
// Double-buffered smem, ONE __syncthreads per k-iter.
// g-tiles overlap (g0 = 0,128,172) so N=300 is covered with dense tiles.
// =====================================================================
__global__ void __launch_bounds__(256) k_embed_ux(
    const int* __restrict__ tokens, const float* __restrict__ emb,
    const float* __restrict__ U)
{
    __shared__ int   ts[128];
    __shared__ float xs[2][8][132];   // xs[buf][k][m]
    __shared__ float us[2][8][132];   // us[buf][k][g]

    const int t  = threadIdx.x;
    const int m0 = blockIdx.x * 128;
    const int g0 = (blockIdx.y < 2) ? blockIdx.y * 128 : (HH - 128); // 0,128,172

    if (t < 128) ts[t] = tokens[m0 + t];
    __syncthreads();

    float acc[8][8];
#pragma unroll
    for (int i = 0; i < 8; i++)
#pragma unroll
        for (int j = 0; j < 8; j++) acc[i][j] = 0.f;

    const int lm   = t & 127;      // loader row
    const int part = t >> 7;       // loader k-half (0/1)
    const int tx   = t & 15;       // compute g-group
    const int ty   = t >> 4;       // compute m-group

    const size_t erow = (size_t)ts[lm] * HH;
    const size_t urow = (size_t)(g0 + lm) * HH;

    const int NIT = 38;            // ceil(300/8)

    float4 xv, uv;
    {
        const int kk = part * 4;
        xv = *(const float4*)(emb + erow + kk);
        uv = *(const float4*)(U   + urow + kk);
        xs[0][part*4+0][lm] = xv.x; xs[0][part*4+1][lm] = xv.y;
        xs[0][part*4+2][lm] = xv.z; xs[0][part*4+3][lm] = xv.w;
        us[0][part*4+0][lm] = uv.x; us[0][part*4+1][lm] = uv.y;
        us[0][part*4+2][lm] = uv.z; us[0][part*4+3][lm] = uv.w;
    }

    for (int it = 0; it < NIT; it++) {
        __syncthreads();

        if (it + 1 < NIT) {
            const int kk = (it + 1) * 8 + part * 4;
            if (kk <= HH - 4) {
                xv = *(const float4*)(emb + erow + kk);
                uv = *(const float4*)(U   + urow + kk);
            } else {
                xv = make_float4(0.f,0.f,0.f,0.f);
                uv = make_float4(0.f,0.f,0.f,0.f);
            }
        }

        const int cb = it & 1;
#pragma unroll
        for (int k = 0; k < 8; k++) {
            float4 a0 = *(const float4*)&xs[cb][k][ty * 8];
            float4 a1 = *(const float4*)&xs[cb][k][ty * 8 + 4];
            float4 b0 = *(const float4*)&us[cb][k][tx * 8];
            float4 b1 = *(const float4*)&us[cb][k][tx * 8 + 4];
            float xr[8] = {a0.x, a0.y, a0.z, a0.w, a1.x, a1.y, a1.z, a1.w};
            float ur[8] = {b0.x, b0.y, b0.z, b0.w, b1.x, b1.y, b1.z, b1.w};
#pragma unroll
            for (int i = 0; i < 8; i++)
#pragma unroll
                for (int j = 0; j < 8; j++)
                    acc[i][j] = fmaf(xr[i], ur[j], acc[i][j]);
        }

        if (it + 1 < NIT) {
            const int nb = (it + 1) & 1;
            xs[nb][part*4+0][lm] = xv.x; xs[nb][part*4+1][lm] = xv.y;
            xs[nb][part*4+2][lm] = xv.z; xs[nb][part*4+3][lm] = xv.w;
            us[nb][part*4+0][lm] = uv.x; us[nb][part*4+1][lm] = uv.y;
            us[nb][part*4+2][lm] = uv.z; us[nb][part*4+3][lm] = uv.w;
        }
    }

#pragma unroll
    for (int i = 0; i < 8; i++) {
        const int m = m0 + ty * 8 + i;
#pragma unroll
        for (int j = 0; j < 8; j += 4) {
            const int g = g0 + tx * 8 + j;
            float4 v = make_float4(acc[i][j], acc[i][j+1], acc[i][j+2], acc[i][j+3]);
            *(float4*)(g_ux + (size_t)m * HH + g) = v;
        }
    }
}

// =====================================================================
// Kernel 2: recurrence.  ONE CTA per batch element (no cluster, no DSMEM).
// 320 threads. Thread t: pair p=t>>1 -> rows {2p,2p+1}; half q=t&1 ->
// k in [152q, 152q+152).  W: 80 k-cols/row in regs, 72 k-cols/row in smem
// (warp-interleaved float4 layout -> coalesced LDS.128).  h double-buffered
// in smem (304 floats each, zero pad past 300).  Sync = __syncthreads only.
// =====================================================================
__global__ void __launch_bounds__(320, 1)
k_scan(const float* __restrict__ W, const float* __restrict__ ihs)
{
    extern __shared__ float dsm[];
    float4* wl      = (float4*)dsm;                  // WL_F4 float4
    float*  hbuf    = dsm + WL_F4 * 4;               // 2 x 304 floats

    const int t  = threadIdx.x;
    const int b  = blockIdx.x;
    const int w  = t >> 5;
    const int l  = t & 31;
    const int q  = t & 1;
    const int r0 = t & ~1;               // even row of the pair
    const bool active = (t < HH);        // thread owns output row t

    const int kb  = 152 * q;             // reg-part k base (16B aligned)
    const int kbs = kb + KREG;           // smem-part k base (16B aligned)

    // ---- W register slices: rows r0, r0+1, k in [kb, kb+KREG) ----
    float wr0[KREG], wr1[KREG];
#pragma unroll
    for (int j = 0; j < KREG; j++) {
        const int k = kb + j;
        const bool ok = (t < HH) && (k < HH);   // t<HH => r0,r0+1 < HH
        wr0[j] = ok ? W[(size_t)r0       * HH + k] : 0.f;
        wr1[j] = ok ? W[(size_t)(r0 + 1) * HH + k] : 0.f;
    }

    // ---- W smem slices (self-owned slots, warp-interleaved) ----
#pragma unroll
    for (int j = 0; j < NJS; j++) {
#pragma unroll
        for (int r = 0; r < 2; r++) {
            const int row = r0 + r;
            float4 v = make_float4(0.f, 0.f, 0.f, 0.f);
            if (t < HH) {
                const int k = kbs + 4 * j;
                v.x = (k + 0 < HH) ? W[(size_t)row * HH + k + 0] : 0.f;
                v.y = (k + 1 < HH) ? W[(size_t)row * HH + k + 1] : 0.f;
                v.z = (k + 2 < HH) ? W[(size_t)row * HH + k + 2] : 0.f;
                v.w = (k + 3 < HH) ? W[(size_t)row * HH + k + 3] : 0.f;
            }
            wl[((w * NJS + j) * 2 + r) * 32 + l] = v;
        }
    }

    // ---- h buffers: [0] = ihs (pad 0), [1] = 0 ----
    if (t < 304) {
        hbuf[t]       = (t < HH) ? ihs[b * HH + t] : 0.f;
        hbuf[304 + t] = 0.f;
    }
    __syncthreads();

    const float* uxp = g_ux + (size_t)b * TT * HH + t;
    float uxv = active ? __ldg(uxp) : 0.f;     // step 0 prefetched
    float hn  = 0.f;

    for (int step = 0; step < TT; step++) {
        const int cb = step & 1;
        const float* hc = hbuf + cb * 304;

        float aA0 = 0.f, aA1 = 0.f, aA2 = 0.f, aA3 = 0.f;  // row r0 partials
        float aB0 = 0.f, aB1 = 0.f, aB2 = 0.f, aB3 = 0.f;  // row r0+1 partials

        // ---- register-W part: k in [kb, kb+80) ----
        const float4* h4r = (const float4*)(hc + kb);
#pragma unroll
        for (int j = 0; j < NJR; j++) {
            float4 h4 = h4r[j];
            aA0 = fmaf(wr0[4*j+0], h4.x, aA0);
            aA1 = fmaf(wr0[4*j+1], h4.y, aA1);
            aA2 = fmaf(wr0[4*j+2], h4.z, aA2);
            aA3 = fmaf(wr0[4*j+3], h4.w, aA3);
            aB0 = fmaf(wr1[4*j+0], h4.x, aB0);
            aB1 = fmaf(wr1[4*j+1], h4.y, aB1);
            aB2 = fmaf(wr1[4*j+2], h4.z, aB2);
            aB3 = fmaf(wr1[4*j+3], h4.w, aB3);
        }

        // prefetch next step's ux (independent)
        float uxn = 0.f;
        if (active && step + 1 < TT)
            uxn = __ldg(uxp + (size_t)(step + 1) * HH);

        // ---- smem-W part: k in [kbs, kbs+72) ----
        const float4* h4s = (const float4*)(hc + kbs);
        const float4* wlp = wl + (w * NJS) * 2 * 32 + l;
#pragma unroll
        for (int j = 0; j < NJS; j++) {
            float4 h4 = h4s[j];
            float4 v0 = wlp[(j * 2 + 0) * 32];
            float4 v1 = wlp[(j * 2 + 1) * 32];
            aA0 = fmaf(v0.x, h4.x, aA0);
            aA1 = fmaf(v0.y, h4.y, aA1);
            aA2 = fmaf(v0.z, h4.z, aA2);
            aA3 = fmaf(v0.w, h4.w, aA3);
            aB0 = fmaf(v1.x, h4.x, aB0);
            aB1 = fmaf(v1.y, h4.y, aB1);
            aB2 = fmaf(v1.z, h4.z, aB2);
            aB3 = fmaf(v1.w, h4.w, aB3);
        }

        // ---- combine k-halves across the thread pair ----
        float sA = (aA0 + aA1) + (aA2 + aA3);   // row r0 partial (this half)
        float sB = (aB0 + aB1) + (aB2 + aB3);   // row r0+1 partial
        sA += __shfl_xor_sync(0xffffffffu, sA, 1);
        sB += __shfl_xor_sync(0xffffffffu, sB, 1);
        const float tot = q ? sB : sA;          // this thread's row = t

        hn = tanhf(tot + uxv);
        if (active) hbuf[(cb ^ 1) * 304 + t] = hn;
        uxv = uxn;
        __syncthreads();
    }

    if (active) g_h[b * HH + t] = hn;
}

// =====================================================================
// Kernel 3: logits[b][v] = sum_h g_h[b][h] * Wout[v][h] + bout[v]
// CTA: 128 v x 64 b. Thread: 4 v x 8 b. Tk = 8, double-buffered, 1 sync/iter.
// =====================================================================
__global__ void __launch_bounds__(256) k_logits(
    const float* __restrict__ Wout, const float* __restrict__ bout,
    float* __restrict__ out)
{
    __shared__ float hs[2][8][68];    // hs[buf][k][b]
    __shared__ float ws[2][8][132];   // ws[buf][k][v_local]

    const int t  = threadIdx.x;
    const int v0 = blockIdx.x * 128;
    const int tx = t & 31;
    const int ty = t >> 5;

    float acc[8][4];
#pragma unroll
    for (int i = 0; i < 8; i++)
#pragma unroll
        for (int j = 0; j < 4; j++) acc[i][j] = 0.f;

    const int lb   = t & 63;
    const int kq   = t >> 6;
    const int lv   = t & 127;
    const int part = t >> 7;
    const int vg   = v0 + lv;
    const bool vok = (vg < VV);

    const int NIT = 38;

    float2 hv; float4 wv;
    {
        const int k1 = kq * 2;
        hv = *(const float2*)(g_h + lb * HH + k1);
        const int kk = part * 4;
        wv = vok ? *(const float4*)(Wout + (size_t)vg * HH + kk)
                 : make_float4(0.f,0.f,0.f,0.f);
        hs[0][kq*2+0][lb] = hv.x; hs[0][kq*2+1][lb] = hv.y;
        ws[0][part*4+0][lv] = wv.x; ws[0][part*4+1][lv] = wv.y;
        ws[0][part*4+2][lv] = wv.z; ws[0][part*4+3][lv] = wv.w;
    }

    for (int it = 0; it < NIT; it++) {
        __syncthreads();

        if (it + 1 < NIT) {
            const int k0 = (it + 1) * 8;
            const int k1 = k0 + kq * 2;
            hv = (k1 <= HH - 2) ? *(const float2*)(g_h + lb * HH + k1)
                                : make_float2(0.f, 0.f);
            const int kk = k0 + part * 4;
            wv = (vok && kk <= HH - 4)
                     ? *(const float4*)(Wout + (size_t)vg * HH + kk)
                     : make_float4(0.f,0.f,0.f,0.f);
        }

        const int cb = it & 1;
#pragma unroll
        for (int k = 0; k < 8; k++) {
            float4 wr = *(const float4*)&ws[cb][k][tx * 4];
            float4 h0 = *(const float4*)&hs[cb][k][ty * 8];
            float4 h1 = *(const float4*)&hs[cb][k][ty * 8 + 4];
            float hr[8] = {h0.x, h0.y, h0.z, h0.w, h1.x, h1.y, h1.z, h1.w};
            float vr[4] = {wr.x, wr.y, wr.z, wr.w};
#pragma unroll
            for (int i = 0; i < 8; i++)
#pragma unroll
                for (int j = 0; j < 4; j++)
                    acc[i][j] = fmaf(hr[i], vr[j], acc[i][j]);
        }

        if (it + 1 < NIT) {
            const int nbuf = (it + 1) & 1;
            hs[nbuf][kq*2+0][lb] = hv.x; hs[nbuf][kq*2+1][lb] = hv.y;
            ws[nbuf][part*4+0][lv] = wv.x; ws[nbuf][part*4+1][lv] = wv.y;
            ws[nbuf][part*4+2][lv] = wv.z; ws[nbuf][part*4+3][lv] = wv.w;
        }
    }

    float bo[4];
#pragma unroll
    for (int j = 0; j < 4; j++) {
        const int v = v0 + tx * 4 + j;
        bo[j] = (v < VV) ? bout[v] : 0.f;
    }
#pragma unroll
    for (int i = 0; i < 8; i++) {
        const int bb = ty * 8 + i;
#pragma unroll
        for (int j = 0; j < 4; j++) {
            const int v = v0 + tx * 4 + j;
            if (v < VV) out[(size_t)bb * VV + v] = acc[i][j] + bo[j];
        }
    }
}

// =====================================================================
extern "C" void kernel_launch(void* const* d_in, const int* in_sizes, int n_in,
                              void* d_out, int out_size)
{
    const float* ihs  = (const float*)d_in[0];
    const int*   tok  = (const int*)  d_in[1];
    const float* emb  = (const float*)d_in[2];
    const float* W    = (const float*)d_in[3];
    const float* U    = (const float*)d_in[4];
    const float* Wout = (const float*)d_in[5];
    const float* bout = (const float*)d_in[6];
    float* out = (float*)d_out;

    cudaFuncSetAttribute(k_scan, cudaFuncAttributeMaxDynamicSharedMemorySize,
                         SCAN_SMEM_BYTES);

    k_embed_ux<<<dim3((BB * TT) / 128, 3), 256>>>(tok, emb, U);
    k_scan<<<BB, 320, SCAN_SMEM_BYTES>>>(W, ihs);
    k_logits<<<(VV + 127) / 128, 256>>>(Wout, bout, out);
}

// round 6
// speedup vs baseline: 1.5642x; 1.5642x over previous
#include <cuda_runtime.h>
#include <cuda_bf16.h>
#include <cstdint>

#define BB 64
#define TT 512
#define HH 300
#define VV 50257

// Scratch (allocation-free: __device__ globals)
__device__ float g_ux[BB * TT * HH];   // [B*T, H] input projections
__device__ float g_h[BB * HH];         // final hidden state

// =====================================================================
// Kernel 1: ux[m, g] = sum_h emb[tokens[m]][h] * U[g][h]
// Tiled SGEMM with gather. CTA tile: 128 m x 128 g, Tk = 8.
// Double-buffered smem, ONE __syncthreads per k-iter.
// g-tiles overlap (g0 = 0,128,172) so N=300 is covered with dense tiles.
// =====================================================================
__global__ void __launch_bounds__(256) k_embed_ux(
    const int* __restrict__ tokens, const float* __restrict__ emb,
    const float* __restrict__ U)
{
    __shared__ int   ts[128];
    __shared__ float xs[2][8][132];   // xs[buf][k][m]
    __shared__ float us[2][8][132];   // us[buf][k][g]

    const int t  = threadIdx.x;
    const int m0 = blockIdx.x * 128;
    const int g0 = (blockIdx.y < 2) ? blockIdx.y * 128 : (HH - 128); // 0,128,172

    if (t < 128) ts[t] = tokens[m0 + t];
    __syncthreads();

    float acc[8][8];
#pragma unroll
    for (int i = 0; i < 8; i++)
#pragma unroll
        for (int j = 0; j < 8; j++) acc[i][j] = 0.f;

    const int lm   = t & 127;      // loader row
    const int part = t >> 7;       // loader k-half (0/1)
    const int tx   = t & 15;       // compute g-group
    const int ty   = t >> 4;       // compute m-group

    const size_t erow = (size_t)ts[lm] * HH;
    const size_t urow = (size_t)(g0 + lm) * HH;

    const int NIT = 38;            // ceil(300/8)

    float4 xv, uv;
    {
        const int kk = part * 4;
        xv = *(const float4*)(emb + erow + kk);
        uv = *(const float4*)(U   + urow + kk);
        xs[0][part*4+0][lm] = xv.x; xs[0][part*4+1][lm] = xv.y;
        xs[0][part*4+2][lm] = xv.z; xs[0][part*4+3][lm] = xv.w;
        us[0][part*4+0][lm] = uv.x; us[0][part*4+1][lm] = uv.y;
        us[0][part*4+2][lm] = uv.z; us[0][part*4+3][lm] = uv.w;
    }

    for (int it = 0; it < NIT; it++) {
        __syncthreads();   // buf[it&1] stores visible; prior readers done

        if (it + 1 < NIT) {
            const int kk = (it + 1) * 8 + part * 4;
            if (kk <= HH - 4) {
                xv = *(const float4*)(emb + erow + kk);
                uv = *(const float4*)(U   + urow + kk);
            } else {
                xv = make_float4(0.f,0.f,0.f,0.f);
                uv = make_float4(0.f,0.f,0.f,0.f);
            }
        }

        const int cb = it & 1;
#pragma unroll
        for (int k = 0; k < 8; k++) {
            float4 a0 = *(const float4*)&xs[cb][k][ty * 8];
            float4 a1 = *(const float4*)&xs[cb][k][ty * 8 + 4];
            float4 b0 = *(const float4*)&us[cb][k][tx * 8];
            float4 b1 = *(const float4*)&us[cb][k][tx * 8 + 4];
            float xr[8] = {a0.x, a0.y, a0.z, a0.w, a1.x, a1.y, a1.z, a1.w};
            float ur[8] = {b0.x, b0.y, b0.z, b0.w, b1.x, b1.y, b1.z, b1.w};
#pragma unroll
            for (int i = 0; i < 8; i++)
#pragma unroll
                for (int j = 0; j < 8; j++)
                    acc[i][j] = fmaf(xr[i], ur[j], acc[i][j]);
        }

        if (it + 1 < NIT) {
            const int nb = (it + 1) & 1;
            xs[nb][part*4+0][lm] = xv.x; xs[nb][part*4+1][lm] = xv.y;
            xs[nb][part*4+2][lm] = xv.z; xs[nb][part*4+3][lm] = xv.w;
            us[nb][part*4+0][lm] = uv.x; us[nb][part*4+1][lm] = uv.y;
            us[nb][part*4+2][lm] = uv.z; us[nb][part*4+3][lm] = uv.w;
        }
    }

#pragma unroll
    for (int i = 0; i < 8; i++) {
        const int m = m0 + ty * 8 + i;
#pragma unroll
        for (int j = 0; j < 8; j += 4) {
            const int g = g0 + tx * 8 + j;
            float4 v = make_float4(acc[i][j], acc[i][j+1], acc[i][j+2], acc[i][j+3]);
            *(float4*)(g_ux + (size_t)m * HH + g) = v;
        }
    }
}

// =====================================================================
// Kernel 2: recurrence.  2-CTA cluster per batch element.
// Rank 0 owns rows [0,152), rank 1 owns [152,300).  W half in registers.
// Per step: Phase A = dot over LOCAL k-range (no cluster dep),
// SPIN on DSMEM flag (fast path = one broadcast LDS), Phase B = dot over
// PEER k-range, tanh, store local + st.shared::cluster to peer,
// __syncthreads, elected st.release.cluster of peer flag (monotonic step
// counter; release cumulativity orders all threads' remote stores).
// Hardware barrier.cluster used only once at init and once at exit.
// =====================================================================
__global__ void __launch_bounds__(320, 1) __cluster_dims__(2, 1, 1)
k_scan(const float* __restrict__ W, const float* __restrict__ ihs)
{
    __shared__ float hbuf[2][304];
    __shared__ unsigned int flag;      // peer-written step counter

    const int t    = threadIdx.x;
    const int r    = blockIdx.x & 1;
    const int b    = blockIdx.x >> 1;
    const int o_l  = t >> 1;
    const int half = t & 1;

    const int Lb     = r ? 152 : 0;    // local row/k-range base
    const int Pb     = r ? 0 : 152;    // peer  row/k-range base
    const int myLen  = r ? 148 : 152;
    const bool active = (o_l < myLen);
    const int o_g    = Lb + o_l;       // global output row

    const int wLbase = Lb + half * 76; // 16B-aligned float4 bases
    const int wPbase = Pb + half * 76;

    // W slices into registers: 76 local-range + 76 peer-range coeffs
    float wl[76], wp[76];
#pragma unroll
    for (int j = 0; j < 76; j++) {
        const int kL = wLbase + j;
        const int kP = wPbase + j;
        wl[j] = (active && kL < HH) ? W[(size_t)o_g * HH + kL] : 0.f;
        wp[j] = (active && kP < HH) ? W[(size_t)o_g * HH + kP] : 0.f;
    }

    // Init BOTH h buffers fully (pad region stays 0 forever)
    if (t < 304) {
        hbuf[0][t] = (t < HH) ? ihs[b * HH + t] : 0.f;
        hbuf[1][t] = 0.f;
    }
    if (t == 0) flag = 0u;

    // Local / peer addresses
    uint32_t my_h0, my_fl;
    {
        uint64_t a;
        asm("cvta.to.shared.u64 %0, %1;" : "=l"(a) : "l"(&hbuf[0][0]));
        my_h0 = (uint32_t)a;
        asm("cvta.to.shared.u64 %0, %1;" : "=l"(a) : "l"(&flag));
        my_fl = (uint32_t)a;
    }
    uint32_t ph0, pfl;
    asm("mapa.shared::cluster.u32 %0, %1, %2;" : "=r"(ph0) : "r"(my_h0), "r"(r ^ 1));
    asm("mapa.shared::cluster.u32 %0, %1, %2;" : "=r"(pfl) : "r"(my_fl), "r"(r ^ 1));
    const uint32_t ph1 = ph0 + 304 * 4;

    // ONE full cluster sync: init (incl. flag=0) visible cluster-wide
    asm volatile("barrier.cluster.arrive.aligned;" ::: "memory");
    asm volatile("barrier.cluster.wait.aligned;"   ::: "memory");

    const float* uxp = g_ux + (size_t)b * TT * HH;
    float hn  = 0.f;
    float uxv = active ? __ldg(uxp + o_g) : 0.f;   // step 0 prefetched

    for (int step = 0; step < TT; step++) {
        const int cb = step & 1;
        const float* hp = &hbuf[cb][0];

        // ---- Phase A: local k-range (written by own CTA last step) ----
        float a0 = 0.f, a1 = 0.f, a2 = 0.f, a3 = 0.f;
        const float* hl = hp + wLbase;
#pragma unroll
        for (int j = 0; j < 76; j += 4) {
            float4 hv = *(const float4*)(hl + j);
            a0 = fmaf(wl[j + 0], hv.x, a0);
            a1 = fmaf(wl[j + 1], hv.y, a1);
            a2 = fmaf(wl[j + 2], hv.z, a2);
            a3 = fmaf(wl[j + 3], hv.w, a3);
        }

        // prefetch next step's ux (independent)
        float uxn = 0.f;
        if (active && step + 1 < TT)
            uxn = __ldg(uxp + (size_t)(step + 1) * HH + o_g);

        // ---- spin until peer delivered its half of buffer cb ----
        // (flag is monotonic: peer sets it to s+1 at end of its step s)
        {
            unsigned int v;
            do {
                asm volatile("ld.acquire.cluster.shared::cta.b32 %0, [%1];"
                             : "=r"(v) : "r"(my_fl) : "memory");
            } while (v < (unsigned int)step);
        }

        // ---- Phase B: peer k-range ----
        const float* hq = hp + wPbase;
#pragma unroll
        for (int j = 0; j < 76; j += 4) {
            float4 hv = *(const float4*)(hq + j);
            a0 = fmaf(wp[j + 0], hv.x, a0);
            a1 = fmaf(wp[j + 1], hv.y, a1);
            a2 = fmaf(wp[j + 2], hv.z, a2);
            a3 = fmaf(wp[j + 3], hv.w, a3);
        }
        float acc = (a0 + a1) + (a2 + a3);
        acc += __shfl_xor_sync(0xffffffffu, acc, 1);   // combine k-halves

        const int nb = cb ^ 1;
        hn = tanhf(acc + uxv);
        if (active && half == 0) {
            hbuf[nb][o_g] = hn;                         // local copy
            if (step + 1 < TT) {
                const uint32_t pdst = (nb ? ph1 : ph0) + (uint32_t)o_g * 4u;
                asm volatile("st.shared::cluster.f32 [%0], %1;"
                             :: "r"(pdst), "f"(hn) : "memory");
            }
        }
        __syncthreads();    // local stores visible CTA-wide; remote stores
                            // happen-before the elected release below
        if (t == 0 && step + 1 < TT) {
            asm volatile("st.release.cluster.shared::cluster.b32 [%0], %1;"
                         :: "r"(pfl), "r"((unsigned int)(step + 1)) : "memory");
        }
        uxv = uxn;
    }

    if (active && half == 0) g_h[b * HH + o_g] = hn;

    // Exit fence: no CTA leaves while peer may still touch our SMEM
    asm volatile("barrier.cluster.arrive.aligned;" ::: "memory");
    asm volatile("barrier.cluster.wait.aligned;"   ::: "memory");
}

// =====================================================================
// Kernel 3: logits[b][v] = sum_h g_h[b][h] * Wout[v][h] + bout[v]
// CTA: 128 v x 64 b. Thread: 4 v x 8 b. Tk = 8, double-buffered, 1 sync/iter.
// =====================================================================
__global__ void __launch_bounds__(256) k_logits(
    const float* __restrict__ Wout, const float* __restrict__ bout,
    float* __restrict__ out)
{
    __shared__ float hs[2][8][68];    // hs[buf][k][b]
    __shared__ float ws[2][8][132];   // ws[buf][k][v_local]

    const int t  = threadIdx.x;
    const int v0 = blockIdx.x * 128;
    const int tx = t & 31;
    const int ty = t >> 5;

    float acc[8][4];
#pragma unroll
    for (int i = 0; i < 8; i++)
#pragma unroll
        for (int j = 0; j < 4; j++) acc[i][j] = 0.f;

    const int lb   = t & 63;
    const int kq   = t >> 6;
    const int lv   = t & 127;
    const int part = t >> 7;
    const int vg   = v0 + lv;
    const bool vok = (vg < VV);

    const int NIT = 38;

    float2 hv; float4 wv;
    {
        const int k1 = kq * 2;
        hv = *(const float2*)(g_h + lb * HH + k1);
        const int kk = part * 4;
        wv = vok ? *(const float4*)(Wout + (size_t)vg * HH + kk)
                 : make_float4(0.f,0.f,0.f,0.f);
        hs[0][kq*2+0][lb] = hv.x; hs[0][kq*2+1][lb] = hv.y;
        ws[0][part*4+0][lv] = wv.x; ws[0][part*4+1][lv] = wv.y;
        ws[0][part*4+2][lv] = wv.z; ws[0][part*4+3][lv] = wv.w;
    }

    for (int it = 0; it < NIT; it++) {
        __syncthreads();

        if (it + 1 < NIT) {
            const int k0 = (it + 1) * 8;
            const int k1 = k0 + kq * 2;
            hv = (k1 <= HH - 2) ? *(const float2*)(g_h + lb * HH + k1)
                                : make_float2(0.f, 0.f);
            const int kk = k0 + part * 4;
            wv = (vok && kk <= HH - 4)
                     ? *(const float4*)(Wout + (size_t)vg * HH + kk)
                     : make_float4(0.f,0.f,0.f,0.f);
        }

        const int cb = it & 1;
#pragma unroll
        for (int k = 0; k < 8; k++) {
            float4 wr = *(const float4*)&ws[cb][k][tx * 4];
            float4 h0 = *(const float4*)&hs[cb][k][ty * 8];
            float4 h1 = *(const float4*)&hs[cb][k][ty * 8 + 4];
            float hr[8] = {h0.x, h0.y, h0.z, h0.w, h1.x, h1.y, h1.z, h1.w};
            float vr[4] = {wr.x, wr.y, wr.z, wr.w};
#pragma unroll
            for (int i = 0; i < 8; i++)
#pragma unroll
                for (int j = 0; j < 4; j++)
                    acc[i][j] = fmaf(hr[i], vr[j], acc[i][j]);
        }

        if (it + 1 < NIT) {
            const int nbuf = (it + 1) & 1;
            hs[nbuf][kq*2+0][lb] = hv.x; hs[nbuf][kq*2+1][lb] = hv.y;
            ws[nbuf][part*4+0][lv] = wv.x; ws[nbuf][part*4+1][lv] = wv.y;
            ws[nbuf][part*4+2][lv] = wv.z; ws[nbuf][part*4+3][lv] = wv.w;
        }
    }

    float bo[4];
#pragma unroll
    for (int j = 0; j < 4; j++) {
        const int v = v0 + tx * 4 + j;
        bo[j] = (v < VV) ? bout[v] : 0.f;
    }
#pragma unroll
    for (int i = 0; i < 8; i++) {
        const int bb = ty * 8 + i;
#pragma unroll
        for (int j = 0; j < 4; j++) {
            const int v = v0 + tx * 4 + j;
            if (v < VV) out[(size_t)bb * VV + v] = acc[i][j] + bo[j];
        }
    }
}

// =====================================================================
extern "C" void kernel_launch(void* const* d_in, const int* in_sizes, int n_in,
                              void* d_out, int out_size)
{
    const float* ihs  = (const float*)d_in[0];
    const int*   tok  = (const int*)  d_in[1];
    const float* emb  = (const float*)d_in[2];
    const float* W    = (const float*)d_in[3];
    const float* U    = (const float*)d_in[4];
    const float* Wout = (const float*)d_in[5];
    const float* bout = (const float*)d_in[6];
    float* out = (float*)d_out;

    k_embed_ux<<<dim3((BB * TT) / 128, 3), 256>>>(tok, emb, U);
    k_scan<<<BB * 2, 320>>>(W, ihs);
    k_logits<<<(VV + 127) / 128, 256>>>(Wout, bout, out);
}